// round 3
// baseline (speedup 1.0000x reference)
#include <cuda_runtime.h>
#include <cuda_bf16.h>

// SoftPool2d: 3x3 window, stride 2, pad 1, zero-padding participates in softmax.
// x: [16, 96, 224, 224] f32, raw_alpha: scalar f32 (alpha = softplus(raw_alpha)).
// out: [16, 96, 112, 112] f32.
// out[p] = sum_i v_i * exp(alpha*v_i) / sum_i exp(alpha*v_i), v_i = window (0 if OOB).

#define H_IN    224
#define W_IN    224
#define H_OUT   112
#define W_OUT   112
#define PLANE_IN  (H_IN * W_IN)     // 50176
#define PLANE_OUT (H_OUT * W_OUT)   // 12544
#define TOTAL_OUT (16 * 96 * PLANE_OUT)  // 19267584

// alpha * log2(e), computed once on device (raw_alpha is device data; no sync copies allowed)
__device__ float g_cl2;

__global__ void softpool_prep(const float* __restrict__ raw_alpha) {
    // softplus(raw) = log1p(exp(raw)); scale by log2(e) so hot loop uses ex2 directly
    float a = log1pf(expf(raw_alpha[0]));
    g_cl2 = a * 1.44269504088896340736f;
}

__device__ __forceinline__ float ex2f(float x) {
    float r;
    asm("ex2.approx.ftz.f32 %0, %1;" : "=f"(r) : "f"(x));
    return r;
}

__device__ __forceinline__ float frcp(float x) {
    float r;
    asm("rcp.approx.ftz.f32 %0, %1;" : "=f"(r) : "f"(x));
    return r;
}

__global__ __launch_bounds__(256, 8)
void softpool_kernel(const float* __restrict__ x, float* __restrict__ out) {
    unsigned idx = blockIdx.x * 256u + threadIdx.x;
    if (idx >= TOTAL_OUT) return;

    unsigned w  = idx % (unsigned)W_OUT;
    unsigned t  = idx / (unsigned)W_OUT;
    unsigned h  = t % (unsigned)H_OUT;
    unsigned nc = t / (unsigned)H_OUT;

    const float* plane = x + (size_t)nc * PLANE_IN;

    // window rows 2h-1..2h+1, cols 2w-1..2w+1. Only rm<0 / cm<0 can be OOB
    // (2*111+1 = 223 < 224, so bottom/right never pad).
    int rm = (int)(2u * h) - 1;
    int cm = (int)(2u * w) - 1;
    int r0i = rm < 0 ? 0 : rm;       // clamp for safe address; value zeroed below
    int c0i = cm < 0 ? 0 : cm;

    const float* r0 = plane + (size_t)r0i * W_IN;
    const float* r1 = plane + (size_t)(rm + 1) * W_IN;
    const float* r2 = plane + (size_t)(rm + 2) * W_IN;

    float v00 = __ldg(r0 + c0i);
    float v01 = __ldg(r0 + (cm + 1));
    float v02 = __ldg(r0 + (cm + 2));
    float v10 = __ldg(r1 + c0i);
    float v11 = __ldg(r1 + (cm + 1));
    float v12 = __ldg(r1 + (cm + 2));
    float v20 = __ldg(r2 + c0i);
    float v21 = __ldg(r2 + (cm + 1));
    float v22 = __ldg(r2 + (cm + 2));

    // zero padded taps (branch-free selects)
    if (rm < 0) { v00 = 0.f; v01 = 0.f; v02 = 0.f; }
    if (cm < 0) { v00 = 0.f; v10 = 0.f; v20 = 0.f; }

    const float c = g_cl2;

    float num = 0.f, den = 0.f;
#define SP_TAP(v) do { float e_ = ex2f(c * (v)); num = fmaf((v), e_, num); den += e_; } while (0)
    SP_TAP(v00); SP_TAP(v01); SP_TAP(v02);
    SP_TAP(v10); SP_TAP(v11); SP_TAP(v12);
    SP_TAP(v20); SP_TAP(v21); SP_TAP(v22);
#undef SP_TAP

    out[idx] = num * frcp(den);
}

extern "C" void kernel_launch(void* const* d_in, const int* in_sizes, int n_in,
                              void* d_out, int out_size) {
    const float* x         = (const float*)d_in[0];
    const float* raw_alpha = (const float*)d_in[1];
    float*       out       = (float*)d_out;

    softpool_prep<<<1, 1>>>(raw_alpha);

    const int total = TOTAL_OUT;
    const int block = 256;
    const int grid  = (total + block - 1) / block;  // 75264
    softpool_kernel<<<grid, block>>>(x, out);
}

// round 4
// speedup vs baseline: 1.3303x; 1.3303x over previous
#include <cuda_runtime.h>
#include <cuda_bf16.h>

// SoftPool2d: 3x3 window, stride 2, pad 1; zero-padding participates in softmax.
// x: [16,96,224,224] f32 -> out: [16,96,112,112] f32.
// Each thread computes a 2x2 output tile from a 5x5 input patch (25 unique taps
// vs 36 for 4 independent outputs): EX2 count -31%, load instrs -58%.

#define H_IN    224
#define W_IN    224
#define H_OUT   112
#define W_OUT   112
#define PLANE_IN  (H_IN * W_IN)     // 50176
#define PLANE_OUT (H_OUT * W_OUT)   // 12544
#define PQ        56                 // output pairs per dim
#define TILES_PER_PLANE (PQ * PQ)    // 3136
#define N_PLANES  (16 * 96)          // 1536
#define TOTAL_TILES (TILES_PER_PLANE * N_PLANES)  // 4,816,896

// alpha * log2(e), computed once on device (raw_alpha is device data)
__device__ float g_cl2;

__global__ void softpool_prep(const float* __restrict__ raw_alpha) {
    float a = log1pf(expf(raw_alpha[0]));   // softplus
    g_cl2 = a * 1.44269504088896340736f;    // * log2(e) for ex2
}

__device__ __forceinline__ float ex2f(float x) {
    float r;
    asm("ex2.approx.ftz.f32 %0, %1;" : "=f"(r) : "f"(x));
    return r;
}

__device__ __forceinline__ float frcp(float x) {
    float r;
    asm("rcp.approx.ftz.f32 %0, %1;" : "=f"(r) : "f"(x));
    return r;
}

__global__ __launch_bounds__(256)
void softpool_kernel(const float* __restrict__ x, float* __restrict__ out) {
    unsigned idx = blockIdx.x * 256u + threadIdx.x;
    if (idx >= TOTAL_TILES) return;

    unsigned p  = idx % PQ;          // output col pair: cols 2p, 2p+1
    unsigned t  = idx / PQ;
    unsigned q  = t % PQ;            // output row pair: rows 2q, 2q+1
    unsigned nc = t / PQ;

    const float* plane = x + (size_t)nc * PLANE_IN;

    // Input patch: rows 4q-1..4q+3, cols 4p-1..4p+3.
    // Max row/col index = 4*55+3 = 223 -> only top/left ever pad.
    int row0 = 4 * (int)q - 1;
    int col0 = 4 * (int)p - 2;       // base addr of first float2 (col0 .x unused)
    int colA = col0 < 0 ? 0 : col0;  // clamped, 8B-aligned either way
    bool left = (p == 0);
    bool top  = (q == 0);

    const float c = g_cl2;

    float num00 = 0.f, num01 = 0.f, num10 = 0.f, num11 = 0.f;
    float den00 = 0.f, den01 = 0.f, den10 = 0.f, den11 = 0.f;

#pragma unroll
    for (int r = 0; r < 5; ++r) {
        int rr = row0 + r;
        int rc = rr < 0 ? 0 : rr;    // clamp addr; values zeroed below
        const float* rp = plane + (size_t)rc * W_IN;

        // cols: a=(4p-2,4p-1) b=(4p,4p+1) d=(4p+2,4p+3); need 4p-1..4p+3
        float2 a = *(const float2*)(rp + colA);
        float2 b = *(const float2*)(rp + col0 + 2);
        float2 d = *(const float2*)(rp + col0 + 4);

        float v0 = left ? 0.f : a.y;
        float v1 = b.x, v2 = b.y, v3 = d.x, v4 = d.y;
        if (top && r == 0) { v0 = 0.f; v1 = 0.f; v2 = 0.f; v3 = 0.f; v4 = 0.f; }

        float e0 = ex2f(c * v0), e1 = ex2f(c * v1), e2 = ex2f(c * v2);
        float e3 = ex2f(c * v3), e4 = ex2f(c * v4);

        // left window = cols {0,1,2}, right window = cols {2,3,4}; col 2 shared
        float ve2 = v2 * e2;
        float dl = e0 + e1 + e2;
        float dr = e2 + e3 + e4;
        float nl = fmaf(v0, e0, fmaf(v1, e1, ve2));
        float nr = fmaf(v3, e3, fmaf(v4, e4, ve2));

        // rows 0..2 -> out row 2q; rows 2..4 -> out row 2q+1 (row 2 shared)
        if (r <= 2) { den00 += dl; den01 += dr; num00 += nl; num01 += nr; }
        if (r >= 2) { den10 += dl; den11 += dr; num10 += nl; num11 += nr; }
    }

    float* op = out + (size_t)nc * PLANE_OUT + (size_t)(2u * q) * W_OUT + 2u * p;
    *(float2*)op           = make_float2(num00 * frcp(den00), num01 * frcp(den01));
    *(float2*)(op + W_OUT) = make_float2(num10 * frcp(den10), num11 * frcp(den11));
}

extern "C" void kernel_launch(void* const* d_in, const int* in_sizes, int n_in,
                              void* d_out, int out_size) {
    const float* x         = (const float*)d_in[0];
    const float* raw_alpha = (const float*)d_in[1];
    float*       out       = (float*)d_out;

    softpool_prep<<<1, 1>>>(raw_alpha);

    const int block = 256;
    const int grid  = (TOTAL_TILES + block - 1) / block;  // 18816
    softpool_kernel<<<grid, block>>>(x, out);
}

// round 5
// speedup vs baseline: 1.4183x; 1.0661x over previous
#include <cuda_runtime.h>
#include <cuda_bf16.h>

// SoftPool2d: 3x3 window, stride 2, pad 1; zero-padding participates in softmax.
// x: [16,96,224,224] f32 -> out: [16,96,112,112] f32.
// Single kernel: each thread computes a 2x2 output tile from a 5x5 input patch
// via 10x LDG.128 (16B-aligned), 25 EX2, and per-thread alpha from the identity
//   alpha*log2e = log2(1 + 2^(raw_alpha*log2e))   (softplus folded into MUFU).

#define H_IN    224
#define W_IN    224
#define H_OUT   112
#define W_OUT   112
#define PLANE_IN  (H_IN * W_IN)     // 50176
#define PLANE_OUT (H_OUT * W_OUT)   // 12544
#define PQ        56                 // output pairs per dim
#define TILES_PER_PLANE (PQ * PQ)    // 3136
#define N_PLANES  (16 * 96)          // 1536
#define TOTAL_TILES (TILES_PER_PLANE * N_PLANES)  // 4,816,896

__device__ __forceinline__ float ex2f(float x) {
    float r;
    asm("ex2.approx.ftz.f32 %0, %1;" : "=f"(r) : "f"(x));
    return r;
}

__device__ __forceinline__ float lg2f(float x) {
    float r;
    asm("lg2.approx.ftz.f32 %0, %1;" : "=f"(r) : "f"(x));
    return r;
}

__device__ __forceinline__ float frcp(float x) {
    float r;
    asm("rcp.approx.ftz.f32 %0, %1;" : "=f"(r) : "f"(x));
    return r;
}

__global__ __launch_bounds__(256)
void softpool_kernel(const float* __restrict__ x,
                     const float* __restrict__ raw_alpha,
                     float* __restrict__ out) {
    unsigned idx = blockIdx.x * 256u + threadIdx.x;
    if (idx >= TOTAL_TILES) return;

    // c = alpha * log2(e) = log2(1 + exp(raw_alpha)) -- 2 MUFU + 1 FMA
    const float c = lg2f(1.0f + ex2f(__ldg(raw_alpha) * 1.44269504088896340736f));

    unsigned p  = idx % PQ;          // output col pair: cols 2p, 2p+1
    unsigned t  = idx / PQ;
    unsigned q  = t % PQ;            // output row pair: rows 2q, 2q+1
    unsigned nc = t / PQ;

    const float* plane = x + (size_t)nc * PLANE_IN;

    // Input patch: rows 4q-1..4q+3, cols 4p-1..4p+3.
    // Max index = 4*55+3 = 223 -> only top/left ever pad.
    int row0 = 4 * (int)q - 1;
    int colB = 4 * (int)p;                 // 16B-aligned float4 base (cols 4p..4p+3)
    int colA = colB >= 4 ? colB - 4 : 0;   // cols 4p-4..4p-1 (clamped for p=0, stays aligned)
    bool left = (p == 0);
    bool top  = (q == 0);

    float num00 = 0.f, num01 = 0.f, num10 = 0.f, num11 = 0.f;
    float den00 = 0.f, den01 = 0.f, den10 = 0.f, den11 = 0.f;

#pragma unroll
    for (int r = 0; r < 5; ++r) {
        int rr = row0 + r;
        int rc = rr < 0 ? 0 : rr;          // clamp addr; values zeroed below
        const float* rp = plane + (size_t)rc * W_IN;

        float4 A = *(const float4*)(rp + colA);  // cols 4p-4..4p-1 (need .w)
        float4 B = *(const float4*)(rp + colB);  // cols 4p..4p+3

        float v0 = left ? 0.f : A.w;
        float v1 = B.x, v2 = B.y, v3 = B.z, v4 = B.w;
        if (top && r == 0) { v0 = 0.f; v1 = 0.f; v2 = 0.f; v3 = 0.f; v4 = 0.f; }

        float e0 = ex2f(c * v0), e1 = ex2f(c * v1), e2 = ex2f(c * v2);
        float e3 = ex2f(c * v3), e4 = ex2f(c * v4);

        // left window = cols {0,1,2}, right window = cols {2,3,4}; col 2 shared
        float ve2 = v2 * e2;
        float dl = e0 + e1 + e2;
        float dr = e2 + e3 + e4;
        float nl = fmaf(v0, e0, fmaf(v1, e1, ve2));
        float nr = fmaf(v3, e3, fmaf(v4, e4, ve2));

        // rows 0..2 -> out row 2q; rows 2..4 -> out row 2q+1 (row 2 shared)
        if (r <= 2) { den00 += dl; den01 += dr; num00 += nl; num01 += nr; }
        if (r >= 2) { den10 += dl; den11 += dr; num10 += nl; num11 += nr; }
    }

    float* op = out + (size_t)nc * PLANE_OUT + (size_t)(2u * q) * W_OUT + 2u * p;
    *(float2*)op           = make_float2(num00 * frcp(den00), num01 * frcp(den01));
    *(float2*)(op + W_OUT) = make_float2(num10 * frcp(den10), num11 * frcp(den11));
}

extern "C" void kernel_launch(void* const* d_in, const int* in_sizes, int n_in,
                              void* d_out, int out_size) {
    const float* x         = (const float*)d_in[0];
    const float* raw_alpha = (const float*)d_in[1];
    float*       out       = (float*)d_out;

    const int block = 256;
    const int grid  = (TOTAL_TILES + block - 1) / block;  // 18816
    softpool_kernel<<<grid, block>>>(x, raw_alpha, out);
}

// round 6
// speedup vs baseline: 1.4206x; 1.0016x over previous
#include <cuda_runtime.h>
#include <cuda_bf16.h>

// SoftPool2d: 3x3 window, stride 2, pad 1; zero-padding participates in softmax.
// x: [16,96,224,224] f32 -> out: [16,96,112,112] f32.
// Each thread computes a 2x4 output tile (2 rows x 4 cols) from a 5x9 input
// patch: per row 1 scalar load (left halo) + 2 aligned LDG.128, 9 EX2.
// Per output: 1.875 loads, 5.625 EX2 (vs 2.5 / 6.25 for the 2x2 tiling).
// alpha folded in per-thread: alpha*log2e = log2(1 + 2^(raw*log2e)).

#define H_IN    224
#define W_IN    224
#define H_OUT   112
#define W_OUT   112
#define PLANE_IN  (H_IN * W_IN)     // 50176
#define PLANE_OUT (H_OUT * W_OUT)   // 12544
#define PT        28                 // col quads per plane (112/4)
#define QT        56                 // row pairs per plane (112/2)
#define TILES_PER_PLANE (PT * QT)    // 1568
#define N_PLANES  (16 * 96)          // 1536
#define TOTAL_TILES (TILES_PER_PLANE * N_PLANES)  // 2,408,448 = 9408 * 256 exactly

__device__ __forceinline__ float ex2f(float x) {
    float r;
    asm("ex2.approx.ftz.f32 %0, %1;" : "=f"(r) : "f"(x));
    return r;
}

__device__ __forceinline__ float lg2f(float x) {
    float r;
    asm("lg2.approx.ftz.f32 %0, %1;" : "=f"(r) : "f"(x));
    return r;
}

__device__ __forceinline__ float frcp(float x) {
    float r;
    asm("rcp.approx.ftz.f32 %0, %1;" : "=f"(r) : "f"(x));
    return r;
}

__global__ __launch_bounds__(256)
void softpool_kernel(const float* __restrict__ x,
                     const float* __restrict__ raw_alpha,
                     float* __restrict__ out) {
    unsigned idx = blockIdx.x * 256u + threadIdx.x;   // grid sized exactly

    // c = alpha * log2(e) = log2(1 + exp(raw_alpha))
    const float c = lg2f(1.0f + ex2f(__ldg(raw_alpha) * 1.44269504088896340736f));

    unsigned P  = idx % PT;          // output cols 4P..4P+3
    unsigned t  = idx / PT;
    unsigned q  = t % QT;            // output rows 2q, 2q+1
    unsigned nc = t / QT;

    const float* plane = x + (size_t)nc * PLANE_IN;

    // Input patch: rows 4q-1..4q+3, cols 8P-1..8P+7. Max index 223 -> only
    // top/left ever pad (8*27+7 = 223, 4*55+3 = 223).
    int row0 = 4 * (int)q - 1;
    int colB = 8 * (int)P;                 // 16B-aligned
    int colL = colB >= 1 ? colB - 1 : 0;   // left halo col (clamped for P=0)
    bool left = (P == 0);
    bool top  = (q == 0);

    float n00 = 0.f, n01 = 0.f, n02 = 0.f, n03 = 0.f;
    float n10 = 0.f, n11 = 0.f, n12 = 0.f, n13 = 0.f;
    float d00 = 0.f, d01 = 0.f, d02 = 0.f, d03 = 0.f;
    float d10 = 0.f, d11 = 0.f, d12 = 0.f, d13 = 0.f;

#pragma unroll
    for (int r = 0; r < 5; ++r) {
        int rr = row0 + r;
        int rc = rr < 0 ? 0 : rr;          // clamp addr; values zeroed below
        const float* rp = plane + (size_t)rc * W_IN;

        float  vLr = __ldg(rp + colL);               // col 8P-1
        float4 B   = *(const float4*)(rp + colB);    // cols 8P..8P+3
        float4 C   = *(const float4*)(rp + colB + 4);// cols 8P+4..8P+7

        float v0 = left ? 0.f : vLr;
        float v1 = B.x, v2 = B.y, v3 = B.z, v4 = B.w;
        float v5 = C.x, v6 = C.y, v7 = C.z, v8 = C.w;
        if (top && r == 0) {
            v0 = 0.f; v1 = 0.f; v2 = 0.f; v3 = 0.f; v4 = 0.f;
            v5 = 0.f; v6 = 0.f; v7 = 0.f; v8 = 0.f;
        }

        float e0 = ex2f(c * v0), e1 = ex2f(c * v1), e2 = ex2f(c * v2);
        float e3 = ex2f(c * v3), e4 = ex2f(c * v4), e5 = ex2f(c * v5);
        float e6 = ex2f(c * v6), e7 = ex2f(c * v7), e8 = ex2f(c * v8);

        // windows j=0..3 use taps {2j, 2j+1, 2j+2}; even taps shared
        float ve2 = v2 * e2, ve4 = v4 * e4, ve6 = v6 * e6;
        float dA = e0 + e1 + e2;
        float dB = e2 + e3 + e4;
        float dC = e4 + e5 + e6;
        float dD = e6 + e7 + e8;
        float nA = fmaf(v0, e0, fmaf(v1, e1, ve2));
        float nB = fmaf(v3, e3, ve2 + ve4);
        float nC = fmaf(v5, e5, ve4 + ve6);
        float nD = fmaf(v7, e7, fmaf(v8, e8, ve6));

        // rows 0..2 -> out row 2q; rows 2..4 -> out row 2q+1 (row 2 shared)
        if (r <= 2) {
            d00 += dA; d01 += dB; d02 += dC; d03 += dD;
            n00 += nA; n01 += nB; n02 += nC; n03 += nD;
        }
        if (r >= 2) {
            d10 += dA; d11 += dB; d12 += dC; d13 += dD;
            n10 += nA; n11 += nB; n12 += nC; n13 += nD;
        }
    }

    float* op = out + (size_t)nc * PLANE_OUT + (size_t)(2u * q) * W_OUT + 4u * P;
    *(float4*)op = make_float4(n00 * frcp(d00), n01 * frcp(d01),
                               n02 * frcp(d02), n03 * frcp(d03));
    *(float4*)(op + W_OUT) = make_float4(n10 * frcp(d10), n11 * frcp(d11),
                                         n12 * frcp(d12), n13 * frcp(d13));
}

extern "C" void kernel_launch(void* const* d_in, const int* in_sizes, int n_in,
                              void* d_out, int out_size) {
    const float* x         = (const float*)d_in[0];
    const float* raw_alpha = (const float*)d_in[1];
    float*       out       = (float*)d_out;

    const int block = 256;
    const int grid  = TOTAL_TILES / block;  // 9408, exact
    softpool_kernel<<<grid, block>>>(x, raw_alpha, out);
}